// round 4
// baseline (speedup 1.0000x reference)
#include <cuda_runtime.h>

// KDE via GEMM trick: density[n] = (1/M) * sum_m exp2( KEXP*(||x||^2+||d||^2) + K2*(x.d) )
// KEXP = -(0.5/sqrt(2*pi))*log2(e),  K2 = -2*KEXP
//
// Inner product uses packed fma.rn.f32x2 (FFMA2): accumulators are f32x2 pairs
// along the m (data) direction. b-pairs come free from double2 smem loads;
// a-splat pairs come free from a DUPLICATED A tile in smem (each value stored
// twice, so an LDS.128 yields two (a,a) splat pairs). Zero packing MOVs in the
// hot loop: per k-step = 6 LDS.128 + 32 FFMA2 for 64 fp32 FMAs/thread.

#define DD   128
#define BN   128
#define BM   128
#define KC   16
#define PAD  4
#define NMAX 8192

__device__ float g_xn2[NMAX];
__device__ float g_dn2[NMAX];

__device__ __forceinline__ float fast_ex2(float x) {
    float y;
    asm("ex2.approx.f32 %0, %1;" : "=f"(y) : "f"(x));
    return y;
}

#define FFMA2(acc, a, b) \
    asm("fma.rn.f32x2 %0, %1, %2, %0;" : "+l"(acc) : "l"(a), "l"(b))

__global__ void norms_kernel(const float* __restrict__ x,
                             const float* __restrict__ data,
                             int N, int M) {
    int i = blockIdx.x * blockDim.x + threadIdx.x;
    if (i < N) {
        const float4* r = reinterpret_cast<const float4*>(x + (size_t)i * DD);
        float s = 0.f;
        #pragma unroll
        for (int j = 0; j < DD / 4; j++) {
            float4 v = r[j];
            s = fmaf(v.x, v.x, s); s = fmaf(v.y, v.y, s);
            s = fmaf(v.z, v.z, s); s = fmaf(v.w, v.w, s);
        }
        g_xn2[i] = s;
    }
    if (i < M) {
        const float4* r = reinterpret_cast<const float4*>(data + (size_t)i * DD);
        float s = 0.f;
        #pragma unroll
        for (int j = 0; j < DD / 4; j++) {
            float4 v = r[j];
            s = fmaf(v.x, v.x, s); s = fmaf(v.y, v.y, s);
            s = fmaf(v.z, v.z, s); s = fmaf(v.w, v.w, s);
        }
        g_dn2[i] = s;
    }
}

__global__ __launch_bounds__(256, 2)
void kde_kernel(const float* __restrict__ x,
                const float* __restrict__ data,
                float* __restrict__ out,
                int N, int M) {
    // A tile stored DUPLICATED: As_dup[k][2r] = As_dup[k][2r+1] = x[n0+r][k0+k]
    __shared__ float As_dup[KC][2 * BN + PAD];  // 16 x 260 floats
    __shared__ float Bs[KC][BM + PAD];          // 16 x 132 floats

    const int tid = threadIdx.x;
    const int tx  = tid & 15;   // m direction: cols tx*4+{0..3}, tx*4+64+{0..3}
    const int ty  = tid >> 4;   // n direction: rows ty*4+{0..3}, ty*4+64+{0..3}
    const int n0  = blockIdx.y * BN;
    const int m0  = blockIdx.x * BM;

    unsigned long long acc2[8][4];
    #pragma unroll
    for (int i = 0; i < 8; i++)
        #pragma unroll
        for (int jp = 0; jp < 4; jp++)
            acc2[i][jp] = 0ULL;

    // Global-load mapping: 256 threads cover 128 rows x 16 k-cols as float4s.
    const int lrow = tid >> 2;   // 0..63 (plus lrow+64)
    const int lc4  = tid & 3;    // float4 index within the 16-wide K chunk

    for (int k0 = 0; k0 < DD; k0 += KC) {
        #pragma unroll
        for (int h = 0; h < 2; h++) {
            const int row = lrow + h * 64;
            float4 va = *reinterpret_cast<const float4*>(
                x + (size_t)(n0 + row) * DD + k0 + lc4 * 4);
            *reinterpret_cast<float2*>(&As_dup[lc4 * 4 + 0][2 * row]) = make_float2(va.x, va.x);
            *reinterpret_cast<float2*>(&As_dup[lc4 * 4 + 1][2 * row]) = make_float2(va.y, va.y);
            *reinterpret_cast<float2*>(&As_dup[lc4 * 4 + 2][2 * row]) = make_float2(va.z, va.z);
            *reinterpret_cast<float2*>(&As_dup[lc4 * 4 + 3][2 * row]) = make_float2(va.w, va.w);
            float4 vb = *reinterpret_cast<const float4*>(
                data + (size_t)(m0 + row) * DD + k0 + lc4 * 4);
            Bs[lc4 * 4 + 0][row] = vb.x;
            Bs[lc4 * 4 + 1][row] = vb.y;
            Bs[lc4 * 4 + 2][row] = vb.z;
            Bs[lc4 * 4 + 3][row] = vb.w;
        }
        __syncthreads();

        #pragma unroll
        for (int k = 0; k < KC; k++) {
            // b pairs: (b0,b1),(b2,b3) from cols tx*4.. and tx*4+64..
            ulonglong2 bL = *reinterpret_cast<const ulonglong2*>(&Bs[k][tx * 4]);
            ulonglong2 bH = *reinterpret_cast<const ulonglong2*>(&Bs[k][tx * 4 + 64]);
            // a splat pairs: (a,a) directly from duplicated tile
            ulonglong2 aL0 = *reinterpret_cast<const ulonglong2*>(&As_dup[k][ty * 8]);
            ulonglong2 aL1 = *reinterpret_cast<const ulonglong2*>(&As_dup[k][ty * 8 + 4]);
            ulonglong2 aH0 = *reinterpret_cast<const ulonglong2*>(&As_dup[k][ty * 8 + 128]);
            ulonglong2 aH1 = *reinterpret_cast<const ulonglong2*>(&As_dup[k][ty * 8 + 132]);

            unsigned long long a2[8] = {aL0.x, aL0.y, aL1.x, aL1.y,
                                        aH0.x, aH0.y, aH1.x, aH1.y};
            unsigned long long b2[4] = {bL.x, bL.y, bH.x, bH.y};

            #pragma unroll
            for (int i = 0; i < 8; i++) {
                FFMA2(acc2[i][0], a2[i], b2[0]);
                FFMA2(acc2[i][1], a2[i], b2[1]);
                FFMA2(acc2[i][2], a2[i], b2[2]);
                FFMA2(acc2[i][3], a2[i], b2[3]);
            }
        }
        __syncthreads();
    }

    // Epilogue: exp2( KEXP*(||x||^2 + ||d||^2) + K2*dot ), sum over m, mean.
    const float KEXP = -0.28777602743432504f;  // -(0.5/sqrt(2pi))*log2(e)
    const float K2   =  0.57555205486865008f;  // -2*KEXP

    float cn[8], cm[8];
    #pragma unroll
    for (int i = 0; i < 8; i++) {
        int row = ty * 4 + (i & 3) + ((i >> 2) << 6);
        cn[i] = KEXP * g_xn2[n0 + row];
    }
    #pragma unroll
    for (int j = 0; j < 8; j++) {
        int col = tx * 4 + (j & 3) + ((j >> 2) << 6);
        cm[j] = KEXP * g_dn2[m0 + col];
    }

    float rs[8];
    #pragma unroll
    for (int i = 0; i < 8; i++) {
        float s = 0.f;
        #pragma unroll
        for (int jp = 0; jp < 4; jp++) {
            // acc2[i][jp] holds cols j = ((jp>>1)<<2) + ((jp&1)<<1) + {0,1}
            int j = ((jp >> 1) << 2) | ((jp & 1) << 1);
            float lo = __uint_as_float((unsigned)(acc2[i][jp] & 0xffffffffULL));
            float hi = __uint_as_float((unsigned)(acc2[i][jp] >> 32));
            s += fast_ex2(fmaf(lo, K2, cn[i] + cm[j]));
            s += fast_ex2(fmaf(hi, K2, cn[i] + cm[j + 1]));
        }
        rs[i] = s;
    }

    // Reduce over the 16 tx lanes (lane bits [3:0]).
    #pragma unroll
    for (int off = 8; off > 0; off >>= 1)
        #pragma unroll
        for (int i = 0; i < 8; i++)
            rs[i] += __shfl_xor_sync(0xffffffffu, rs[i], off);

    if (tx == 0) {
        const float invM = 1.0f / (float)M;
        #pragma unroll
        for (int i = 0; i < 8; i++) {
            int row = ty * 4 + (i & 3) + ((i >> 2) << 6);
            atomicAdd(&out[n0 + row], rs[i] * invM);
        }
    }
}

extern "C" void kernel_launch(void* const* d_in, const int* in_sizes, int n_in,
                              void* d_out, int out_size) {
    const float* x    = (const float*)d_in[0];
    const float* data = (const float*)d_in[1];
    float* out = (float*)d_out;

    const int N = in_sizes[0] / DD;
    const int M = in_sizes[1] / DD;

    cudaMemsetAsync(d_out, 0, (size_t)out_size * sizeof(float));

    const int nmax = (N > M) ? N : M;
    norms_kernel<<<(nmax + 255) / 256, 256>>>(x, data, N, M);

    dim3 grid(M / BM, N / BN);
    kde_kernel<<<grid, 256>>>(x, data, out, N, M);
}

// round 7
// speedup vs baseline: 2.2130x; 2.2130x over previous
#include <cuda_runtime.h>
#include <cuda_bf16.h>
#include <cstdint>

// KDE via bf16 HMMA (mma.sync m16n8k16) GEMM over K=384 (2-term fp32 split):
//   x = hiX + loX (bf16 each), d = hiD + loD
//   dot ~= hiX.hiD + hiX.loD + loX.hiD   (lo.lo dropped, ~5e-5 abs error)
//   Xcat[n] = [hiX | hiX | loX], Dcat[m] = [hiD | loD | hiD]  (384 bf16 rows)
// density[n] = (1/M) * sum_m exp2( KEXP*(||x||^2+||d||^2) + K2*dot )
// NOTE: tcgen05 is unavailable (harness PTX target is sm_103, not sm_103a),
// so this uses the Ampere-style warp MMA path.

#define DD    128
#define NTOT  8192
#define KCAT  384
#define BN    128
#define BM    128
#define KC    64

#define PITCH 144                    // smem row pitch bytes (128B data + 16B pad)
#define ASIZE (128 * PITCH)          // 18432 per matrix per stage
#define STAGE (2 * ASIZE)            // 36864 (A + B)
#define SM_CN (2 * STAGE)            // 73728
#define SM_CM (SM_CN + 512)
#define SM_RS (SM_CM + 512)
#define SMEM_TOTAL (SM_RS + 512)     // 75264

__device__ __align__(16) __nv_bfloat16 g_xcat[NTOT * KCAT];
__device__ __align__(16) __nv_bfloat16 g_dcat[NTOT * KCAT];
__device__ float g_xn2[NTOT];
__device__ float g_dn2[NTOT];

// --------------------------------------------------------------- PTX helpers
__device__ __forceinline__ uint32_t smem_u32(const void* p) {
    uint32_t a;
    asm("{ .reg .u64 t; cvta.to.shared.u64 t, %1; cvt.u32.u64 %0, t; }"
        : "=r"(a) : "l"(p));
    return a;
}

__device__ __forceinline__ void cp_async16(uint32_t sa, const void* ga) {
    asm volatile("cp.async.cg.shared.global [%0], [%1], 16;"
                 :: "r"(sa), "l"(ga) : "memory");
}
#define CP_COMMIT() asm volatile("cp.async.commit_group;" ::: "memory")

__device__ __forceinline__ float fast_ex2(float x) {
    float y;
    asm("ex2.approx.f32 %0, %1;" : "=f"(y) : "f"(x));
    return y;
}

#define LDMX4(r0, r1, r2, r3, adr)                                            \
    asm volatile("ldmatrix.sync.aligned.m8n8.x4.shared.b16 {%0,%1,%2,%3}, [%4];" \
                 : "=r"(r0), "=r"(r1), "=r"(r2), "=r"(r3) : "r"(adr))

#define MMA16816(cc, a0, a1, a2, a3, b0, b1)                                  \
    asm volatile("mma.sync.aligned.m16n8k16.row.col.f32.bf16.bf16.f32 "       \
                 "{%0,%1,%2,%3},{%4,%5,%6,%7},{%8,%9},{%0,%1,%2,%3};"         \
                 : "+f"((cc)[0]), "+f"((cc)[1]), "+f"((cc)[2]), "+f"((cc)[3]) \
                 : "r"(a0), "r"(a1), "r"(a2), "r"(a3), "r"(b0), "r"(b1))

// -------------------------------------------------- convert + norms (warp/row)
__global__ void convert_kernel(const float* __restrict__ x,
                               const float* __restrict__ d) {
    const int gw   = (blockIdx.x * blockDim.x + threadIdx.x) >> 5;
    const int lane = threadIdx.x & 31;
    if (gw >= NTOT) return;

    // ---- x row: [hi | hi | lo] ----
    {
        float4 v = reinterpret_cast<const float4*>(x + (size_t)gw * DD)[lane];
        float nrm = v.x * v.x;
        nrm = fmaf(v.y, v.y, nrm);
        nrm = fmaf(v.z, v.z, nrm);
        nrm = fmaf(v.w, v.w, nrm);
        #pragma unroll
        for (int off = 16; off > 0; off >>= 1)
            nrm += __shfl_xor_sync(0xffffffffu, nrm, off);
        if (lane == 0) g_xn2[gw] = nrm;

        float f[4] = {v.x, v.y, v.z, v.w};
        unsigned short hb[4], lb[4];
        #pragma unroll
        for (int j = 0; j < 4; j++) {
            __nv_bfloat16 h = __float2bfloat16_rn(f[j]);
            __nv_bfloat16 l = __float2bfloat16_rn(f[j] - __bfloat162float(h));
            hb[j] = __bfloat16_as_ushort(h);
            lb[j] = __bfloat16_as_ushort(l);
        }
        uint2 hp = make_uint2((uint32_t)hb[0] | ((uint32_t)hb[1] << 16),
                              (uint32_t)hb[2] | ((uint32_t)hb[3] << 16));
        uint2 lp = make_uint2((uint32_t)lb[0] | ((uint32_t)lb[1] << 16),
                              (uint32_t)lb[2] | ((uint32_t)lb[3] << 16));
        char* base = reinterpret_cast<char*>(g_xcat) + (size_t)gw * 768 + lane * 8;
        *reinterpret_cast<uint2*>(base)       = hp;
        *reinterpret_cast<uint2*>(base + 256) = hp;
        *reinterpret_cast<uint2*>(base + 512) = lp;
    }
    // ---- d row: [hi | lo | hi] ----
    {
        float4 v = reinterpret_cast<const float4*>(d + (size_t)gw * DD)[lane];
        float nrm = v.x * v.x;
        nrm = fmaf(v.y, v.y, nrm);
        nrm = fmaf(v.z, v.z, nrm);
        nrm = fmaf(v.w, v.w, nrm);
        #pragma unroll
        for (int off = 16; off > 0; off >>= 1)
            nrm += __shfl_xor_sync(0xffffffffu, nrm, off);
        if (lane == 0) g_dn2[gw] = nrm;

        float f[4] = {v.x, v.y, v.z, v.w};
        unsigned short hb[4], lb[4];
        #pragma unroll
        for (int j = 0; j < 4; j++) {
            __nv_bfloat16 h = __float2bfloat16_rn(f[j]);
            __nv_bfloat16 l = __float2bfloat16_rn(f[j] - __bfloat162float(h));
            hb[j] = __bfloat16_as_ushort(h);
            lb[j] = __bfloat16_as_ushort(l);
        }
        uint2 hp = make_uint2((uint32_t)hb[0] | ((uint32_t)hb[1] << 16),
                              (uint32_t)hb[2] | ((uint32_t)hb[3] << 16));
        uint2 lp = make_uint2((uint32_t)lb[0] | ((uint32_t)lb[1] << 16),
                              (uint32_t)lb[2] | ((uint32_t)lb[3] << 16));
        char* base = reinterpret_cast<char*>(g_dcat) + (size_t)gw * 768 + lane * 8;
        *reinterpret_cast<uint2*>(base)       = hp;
        *reinterpret_cast<uint2*>(base + 256) = lp;
        *reinterpret_cast<uint2*>(base + 512) = hp;
    }
}

// ---------------------------------------------------------------- main kernel
__global__ void __launch_bounds__(256)
kde_kernel(float* __restrict__ out) {
    extern __shared__ char smem[];
    const uint32_t sb = smem_u32(smem);
    const int tid  = threadIdx.x;
    const int lane = tid & 31;
    const int wid  = tid >> 5;
    const int wr   = wid & 1;      // n half  (64 rows)
    const int wc   = wid >> 1;     // m quarter (32 cols)
    const int n0   = blockIdx.y * BN;
    const int m0   = blockIdx.x * BM;

    const float KEXP = -0.28777602743432504f;  // -(0.5/sqrt(2pi))*log2(e)
    const float K2   =  0.57555205486865008f;  // -2*KEXP

    float* cnS = reinterpret_cast<float*>(smem + SM_CN);
    float* cmS = reinterpret_cast<float*>(smem + SM_CM);
    float* rsS = reinterpret_cast<float*>(smem + SM_RS);

    if (tid < 128) {
        cnS[tid] = KEXP * g_xn2[n0 + tid];
        cmS[tid] = KEXP * g_dn2[m0 + tid];
        rsS[tid] = 0.f;
    }

    float c[4][4][4];
    #pragma unroll
    for (int rt = 0; rt < 4; rt++)
        #pragma unroll
        for (int ct = 0; ct < 4; ct++)
            #pragma unroll
            for (int q = 0; q < 4; q++)
                c[rt][ct][q] = 0.f;

    const char* ga = reinterpret_cast<const char*>(g_xcat);
    const char* gb = reinterpret_cast<const char*>(g_dcat);

    auto load_chunk = [&](int ch, int s) {
        const uint32_t da = sb + s * STAGE;
        const uint32_t db = da + ASIZE;
        const int koff = ch * KC * 2;
        #pragma unroll
        for (int i = 0; i < 4; i++) {
            int seg = tid + 256 * i;
            int row = seg >> 3, ks = seg & 7;
            cp_async16(da + row * PITCH + ks * 16,
                       ga + (size_t)(n0 + row) * 768 + koff + ks * 16);
            cp_async16(db + row * PITCH + ks * 16,
                       gb + (size_t)(m0 + row) * 768 + koff + ks * 16);
        }
    };

    auto compute_stage = [&](int s) {
        const uint32_t aAddr = sb + s * STAGE +
            (wr * 64 + (lane & 15)) * PITCH + ((lane >> 4) << 4);
        const uint32_t bAddr = sb + s * STAGE + ASIZE +
            (wc * 32 + (lane & 15)) * PITCH + ((lane >> 4) << 4);
        #pragma unroll
        for (int k = 0; k < 4; k++) {
            uint32_t a[4][4];
            #pragma unroll
            for (int rt = 0; rt < 4; rt++)
                LDMX4(a[rt][0], a[rt][1], a[rt][2], a[rt][3],
                      aAddr + rt * 16 * PITCH + k * 32);
            uint32_t b[4][2];
            #pragma unroll
            for (int p = 0; p < 2; p++) {
                uint32_t r0, r1, r2, r3;
                LDMX4(r0, r1, r2, r3, bAddr + p * 16 * PITCH + k * 32);
                b[2 * p][0] = r0; b[2 * p][1] = r2;       // ct even: k0-7, k8-15
                b[2 * p + 1][0] = r1; b[2 * p + 1][1] = r3;
            }
            #pragma unroll
            for (int rt = 0; rt < 4; rt++)
                #pragma unroll
                for (int ct = 0; ct < 4; ct++)
                    MMA16816(c[rt][ct], a[rt][0], a[rt][1], a[rt][2], a[rt][3],
                             b[ct][0], b[ct][1]);
        }
    };

    load_chunk(0, 0);
    CP_COMMIT();

    #pragma unroll 1
    for (int ch = 0; ch < KCAT / KC; ch++) {
        const int s = ch & 1;
        if (ch < KCAT / KC - 1) {
            load_chunk(ch + 1, s ^ 1);
            CP_COMMIT();
            asm volatile("cp.async.wait_group 1;" ::: "memory");
        } else {
            asm volatile("cp.async.wait_group 0;" ::: "memory");
        }
        __syncthreads();
        compute_stage(s);
        __syncthreads();
    }

    // --------- fused epilogue: exp2 + row reduce ---------
    const int rq = lane >> 2;            // 0..7 row within 16-row tile
    const int cq = 2 * (lane & 3);       // 0,2,4,6 col within 8-col tile
    #pragma unroll
    for (int rt = 0; rt < 4; rt++) {
        const int rbase = wr * 64 + rt * 16 + rq;
        const float cn0 = cnS[rbase];
        const float cn1 = cnS[rbase + 8];
        float s0 = 0.f, s1 = 0.f;
        #pragma unroll
        for (int ct = 0; ct < 4; ct++) {
            const int col = wc * 32 + ct * 8 + cq;
            const float cm0 = cmS[col], cm1 = cmS[col + 1];
            s0 += fast_ex2(fmaf(c[rt][ct][0], K2, cn0 + cm0));
            s0 += fast_ex2(fmaf(c[rt][ct][1], K2, cn0 + cm1));
            s1 += fast_ex2(fmaf(c[rt][ct][2], K2, cn1 + cm0));
            s1 += fast_ex2(fmaf(c[rt][ct][3], K2, cn1 + cm1));
        }
        s0 += __shfl_xor_sync(0xffffffffu, s0, 1);
        s0 += __shfl_xor_sync(0xffffffffu, s0, 2);
        s1 += __shfl_xor_sync(0xffffffffu, s1, 1);
        s1 += __shfl_xor_sync(0xffffffffu, s1, 2);
        if ((lane & 3) == 0) {
            atomicAdd(&rsS[rbase], s0);
            atomicAdd(&rsS[rbase + 8], s1);
        }
    }
    __syncthreads();
    if (tid < 128)
        atomicAdd(&out[n0 + tid], rsS[tid] * (1.0f / (float)NTOT));
}

extern "C" void kernel_launch(void* const* d_in, const int* in_sizes, int n_in,
                              void* d_out, int out_size) {
    const float* x    = (const float*)d_in[0];
    const float* data = (const float*)d_in[1];
    float* out = (float*)d_out;

    cudaFuncSetAttribute(kde_kernel,
                         cudaFuncAttributeMaxDynamicSharedMemorySize, SMEM_TOTAL);

    cudaMemsetAsync(d_out, 0, (size_t)out_size * sizeof(float));
    convert_kernel<<<NTOT * 32 / 256, 256>>>(x, data);

    dim3 grid(NTOT / BM, NTOT / BN);
    kde_kernel<<<grid, 256, SMEM_TOTAL>>>(out);
}

// round 8
// speedup vs baseline: 2.6474x; 1.1963x over previous
#include <cuda_runtime.h>
#include <cuda_bf16.h>
#include <cstdint>

// KDE via bf16 HMMA (mma.sync m16n8k16) GEMM over K=384 (2-term fp32 split):
//   Xcat[n] = [hiX | hiX | loX], Dcat[m] = [hiD | loD | hiD]
// density[n] = (1/M) * sum_m exp2( KEXP*(||x||^2+||d||^2) + K2*dot )
// R7: swizzled smem (128B pitch), 3-stage cp.async pipeline w/ 1 sync per
// chunk, 2 CTAs/SM.

#define DD    128
#define NTOT  8192
#define KCAT  384
#define BN    128
#define BM    128
#define KC    64
#define NCH   (KCAT / KC)            // 6

#define ASZ   (128 * 128)            // 16384 bytes: one matrix, one stage
#define STG   (2 * ASZ)              // 32768: A + B per stage
#define SM_CN (3 * STG)              // after 3 stages = 98304
#define SM_CM (SM_CN + 512)
#define SM_RS (SM_CM + 512)
#define SMEM_TOTAL (SM_RS + 512)     // 99840

__device__ __align__(16) __nv_bfloat16 g_xcat[NTOT * KCAT];
__device__ __align__(16) __nv_bfloat16 g_dcat[NTOT * KCAT];
__device__ float g_xn2[NTOT];
__device__ float g_dn2[NTOT];

// --------------------------------------------------------------- PTX helpers
__device__ __forceinline__ uint32_t smem_u32(const void* p) {
    uint32_t a;
    asm("{ .reg .u64 t; cvta.to.shared.u64 t, %1; cvt.u32.u64 %0, t; }"
        : "=r"(a) : "l"(p));
    return a;
}

__device__ __forceinline__ void cp_async16(uint32_t sa, const void* ga) {
    asm volatile("cp.async.cg.shared.global [%0], [%1], 16;"
                 :: "r"(sa), "l"(ga) : "memory");
}
#define CP_COMMIT() asm volatile("cp.async.commit_group;" ::: "memory")

__device__ __forceinline__ float fast_ex2(float x) {
    float y;
    asm("ex2.approx.f32 %0, %1;" : "=f"(y) : "f"(x));
    return y;
}

#define LDMX4(r0, r1, r2, r3, adr)                                            \
    asm volatile("ldmatrix.sync.aligned.m8n8.x4.shared.b16 {%0,%1,%2,%3}, [%4];" \
                 : "=r"(r0), "=r"(r1), "=r"(r2), "=r"(r3) : "r"(adr))

#define MMA16816(cc, a0, a1, a2, a3, b0, b1)                                  \
    asm volatile("mma.sync.aligned.m16n8k16.row.col.f32.bf16.bf16.f32 "       \
                 "{%0,%1,%2,%3},{%4,%5,%6,%7},{%8,%9},{%0,%1,%2,%3};"         \
                 : "+f"((cc)[0]), "+f"((cc)[1]), "+f"((cc)[2]), "+f"((cc)[3]) \
                 : "r"(a0), "r"(a1), "r"(a2), "r"(a3), "r"(b0), "r"(b1))

// -------------------------------------------------- convert + norms (warp/row)
__global__ void convert_kernel(const float* __restrict__ x,
                               const float* __restrict__ d) {
    const int gw   = (blockIdx.x * blockDim.x + threadIdx.x) >> 5;
    const int lane = threadIdx.x & 31;
    if (gw >= NTOT) return;

    {   // x row: [hi | hi | lo]
        float4 v = reinterpret_cast<const float4*>(x + (size_t)gw * DD)[lane];
        float nrm = v.x * v.x;
        nrm = fmaf(v.y, v.y, nrm);
        nrm = fmaf(v.z, v.z, nrm);
        nrm = fmaf(v.w, v.w, nrm);
        #pragma unroll
        for (int off = 16; off > 0; off >>= 1)
            nrm += __shfl_xor_sync(0xffffffffu, nrm, off);
        if (lane == 0) g_xn2[gw] = nrm;

        float f[4] = {v.x, v.y, v.z, v.w};
        unsigned short hb[4], lb[4];
        #pragma unroll
        for (int j = 0; j < 4; j++) {
            __nv_bfloat16 h = __float2bfloat16_rn(f[j]);
            __nv_bfloat16 l = __float2bfloat16_rn(f[j] - __bfloat162float(h));
            hb[j] = __bfloat16_as_ushort(h);
            lb[j] = __bfloat16_as_ushort(l);
        }
        uint2 hp = make_uint2((uint32_t)hb[0] | ((uint32_t)hb[1] << 16),
                              (uint32_t)hb[2] | ((uint32_t)hb[3] << 16));
        uint2 lp = make_uint2((uint32_t)lb[0] | ((uint32_t)lb[1] << 16),
                              (uint32_t)lb[2] | ((uint32_t)lb[3] << 16));
        char* base = reinterpret_cast<char*>(g_xcat) + (size_t)gw * 768 + lane * 8;
        *reinterpret_cast<uint2*>(base)       = hp;
        *reinterpret_cast<uint2*>(base + 256) = hp;
        *reinterpret_cast<uint2*>(base + 512) = lp;
    }
    {   // d row: [hi | lo | hi]
        float4 v = reinterpret_cast<const float4*>(d + (size_t)gw * DD)[lane];
        float nrm = v.x * v.x;
        nrm = fmaf(v.y, v.y, nrm);
        nrm = fmaf(v.z, v.z, nrm);
        nrm = fmaf(v.w, v.w, nrm);
        #pragma unroll
        for (int off = 16; off > 0; off >>= 1)
            nrm += __shfl_xor_sync(0xffffffffu, nrm, off);
        if (lane == 0) g_dn2[gw] = nrm;

        float f[4] = {v.x, v.y, v.z, v.w};
        unsigned short hb[4], lb[4];
        #pragma unroll
        for (int j = 0; j < 4; j++) {
            __nv_bfloat16 h = __float2bfloat16_rn(f[j]);
            __nv_bfloat16 l = __float2bfloat16_rn(f[j] - __bfloat162float(h));
            hb[j] = __bfloat16_as_ushort(h);
            lb[j] = __bfloat16_as_ushort(l);
        }
        uint2 hp = make_uint2((uint32_t)hb[0] | ((uint32_t)hb[1] << 16),
                              (uint32_t)hb[2] | ((uint32_t)hb[3] << 16));
        uint2 lp = make_uint2((uint32_t)lb[0] | ((uint32_t)lb[1] << 16),
                              (uint32_t)lb[2] | ((uint32_t)lb[3] << 16));
        char* base = reinterpret_cast<char*>(g_dcat) + (size_t)gw * 768 + lane * 8;
        *reinterpret_cast<uint2*>(base)       = hp;
        *reinterpret_cast<uint2*>(base + 256) = lp;
        *reinterpret_cast<uint2*>(base + 512) = hp;
    }
}

// ---------------------------------------------------------------- main kernel
__global__ void __launch_bounds__(256, 2)
kde_kernel(float* __restrict__ out) {
    extern __shared__ char smem[];
    const uint32_t sb = smem_u32(smem);
    const int tid  = threadIdx.x;
    const int lane = tid & 31;
    const int wid  = tid >> 5;
    const int wr   = wid & 1;      // n half (64 rows)
    const int wc   = wid >> 1;     // m quarter (32 cols)
    const int n0   = blockIdx.y * BN;
    const int m0   = blockIdx.x * BM;

    const float KEXP = -0.28777602743432504f;
    const float K2   =  0.57555205486865008f;

    float* cnS = reinterpret_cast<float*>(smem + SM_CN);
    float* cmS = reinterpret_cast<float*>(smem + SM_CM);
    float* rsS = reinterpret_cast<float*>(smem + SM_RS);

    if (tid < 128) {
        cnS[tid] = KEXP * g_xn2[n0 + tid];
        cmS[tid] = KEXP * g_dn2[m0 + tid];
        rsS[tid] = 0.f;
    }

    float c[4][4][4];
    #pragma unroll
    for (int rt = 0; rt < 4; rt++)
        #pragma unroll
        for (int ct = 0; ct < 4; ct++)
            #pragma unroll
            for (int q = 0; q < 4; q++)
                c[rt][ct][q] = 0.f;

    const char* ga = reinterpret_cast<const char*>(g_xcat);
    const char* gb = reinterpret_cast<const char*>(g_dcat);

    // ---- per-thread store mapping (1024 16B segs per matrix per chunk) ----
    // seg = tid + 256*i : row = seg>>3, w = seg&7, swizzled w' = w ^ (row&7)
    auto load_chunk = [&](int ch, int s) {
        const uint32_t da = sb + s * STG;
        const uint32_t db = da + ASZ;
        const int koff = ch * (KC * 2);
        #pragma unroll
        for (int i = 0; i < 4; i++) {
            int seg = tid + 256 * i;
            int row = seg >> 3, w = seg & 7;
            uint32_t soff = row * 128 + ((w ^ (row & 7)) << 4);
            cp_async16(da + soff, ga + (size_t)(n0 + row) * 768 + koff + w * 16);
            cp_async16(db + soff, gb + (size_t)(m0 + row) * 768 + koff + w * 16);
        }
        CP_COMMIT();
    };

    // ---- per-lane fragment address pieces (stage-independent) ----
    const int h    = lane >> 4;            // 16B half within 32B k-step
    const int rA   = wr * 64 + (lane & 15);
    const int rb7A = rA & 7;
    const int rB   = wc * 32 + (lane & 15);
    const int rb7B = rB & 7;

    auto compute_stage = [&](int s) {
        const uint32_t sA = sb + s * STG + rA * 128;
        const uint32_t sB = sb + s * STG + ASZ + rB * 128;
        #pragma unroll
        for (int k = 0; k < 4; k++) {
            const uint32_t aoff = sA + (((k * 2 + h) ^ rb7A) << 4);
            const uint32_t boff = sB + (((k * 2 + h) ^ rb7B) << 4);
            uint32_t a[4][4];
            #pragma unroll
            for (int rt = 0; rt < 4; rt++)
                LDMX4(a[rt][0], a[rt][1], a[rt][2], a[rt][3], aoff + rt * 2048);
            uint32_t b[4][2];
            #pragma unroll
            for (int p = 0; p < 2; p++) {
                uint32_t r0, r1, r2, r3;
                LDMX4(r0, r1, r2, r3, boff + p * 2048);
                b[2 * p][0] = r0;     b[2 * p][1] = r2;
                b[2 * p + 1][0] = r1; b[2 * p + 1][1] = r3;
            }
            #pragma unroll
            for (int rt = 0; rt < 4; rt++)
                #pragma unroll
                for (int ct = 0; ct < 4; ct++)
                    MMA16816(c[rt][ct], a[rt][0], a[rt][1], a[rt][2], a[rt][3],
                             b[ct][0], b[ct][1]);
        }
    };

    // ---- 3-stage pipeline, one __syncthreads per chunk ----
    load_chunk(0, 0);
    load_chunk(1, 1);

    #pragma unroll 1
    for (int ch = 0; ch < NCH; ch++) {
        const int s = ch % 3;
        if (ch < NCH - 1)
            asm volatile("cp.async.wait_group 1;" ::: "memory");
        else
            asm volatile("cp.async.wait_group 0;" ::: "memory");
        __syncthreads();
        compute_stage(s);
        if (ch + 2 < NCH) load_chunk(ch + 2, (ch + 2) % 3);
    }

    // --------- fused epilogue: exp2 + row reduce ---------
    const int rq = lane >> 2;
    const int cq = 2 * (lane & 3);
    #pragma unroll
    for (int rt = 0; rt < 4; rt++) {
        const int rbase = wr * 64 + rt * 16 + rq;
        const float cn0 = cnS[rbase];
        const float cn1 = cnS[rbase + 8];
        float s0 = 0.f, s1 = 0.f;
        #pragma unroll
        for (int ct = 0; ct < 4; ct++) {
            const int col = wc * 32 + ct * 8 + cq;
            const float cm0 = cmS[col], cm1 = cmS[col + 1];
            s0 += fast_ex2(fmaf(c[rt][ct][0], K2, cn0 + cm0));
            s0 += fast_ex2(fmaf(c[rt][ct][1], K2, cn0 + cm1));
            s1 += fast_ex2(fmaf(c[rt][ct][2], K2, cn1 + cm0));
            s1 += fast_ex2(fmaf(c[rt][ct][3], K2, cn1 + cm1));
        }
        s0 += __shfl_xor_sync(0xffffffffu, s0, 1);
        s0 += __shfl_xor_sync(0xffffffffu, s0, 2);
        s1 += __shfl_xor_sync(0xffffffffu, s1, 1);
        s1 += __shfl_xor_sync(0xffffffffu, s1, 2);
        if ((lane & 3) == 0) {
            atomicAdd(&rsS[rbase], s0);
            atomicAdd(&rsS[rbase + 8], s1);
        }
    }
    __syncthreads();
    if (tid < 128)
        atomicAdd(&out[n0 + tid], rsS[tid] * (1.0f / (float)NTOT));
}

extern "C" void kernel_launch(void* const* d_in, const int* in_sizes, int n_in,
                              void* d_out, int out_size) {
    const float* x    = (const float*)d_in[0];
    const float* data = (const float*)d_in[1];
    float* out = (float*)d_out;

    cudaFuncSetAttribute(kde_kernel,
                         cudaFuncAttributeMaxDynamicSharedMemorySize, SMEM_TOTAL);

    cudaMemsetAsync(d_out, 0, (size_t)out_size * sizeof(float));
    convert_kernel<<<NTOT * 32 / 256, 256>>>(x, data);

    dim3 grid(NTOT / BM, NTOT / BN);
    kde_kernel<<<grid, 256, SMEM_TOTAL>>>(out);
}

// round 9
// speedup vs baseline: 2.8213x; 1.0657x over previous
#include <cuda_runtime.h>
#include <cuda_bf16.h>
#include <cstdint>

// KDE via bf16 HMMA (mma.sync m16n8k16) GEMM over K=384 (2-term fp32 split):
//   Xcat[n] = [hiX | hiX | loX], Dcat[m] = [hiD | loD | hiD]
// density[n] = (1/M) * sum_m exp2( KEXP*(||x||^2+||d||^2) + K2*dot )
// R8: fully-unrolled chunk loop (immediate addresses), precomputed swizzled
// LDSM offsets, b-fragment double-buffer prefetch. 3-stage cp.async pipeline,
// 1 syncthreads per chunk, 2 CTAs/SM.

#define DD    128
#define NTOT  8192
#define KCAT  384
#define BN    128
#define BM    128
#define KC    64
#define NCH   (KCAT / KC)            // 6

#define ASZ   (128 * 128)            // 16384 B: one matrix, one stage
#define STG   (2 * ASZ)              // 32768: A + B per stage
#define SM_CN (3 * STG)              // 98304
#define SM_CM (SM_CN + 512)
#define SM_RS (SM_CM + 512)
#define SMEM_TOTAL (SM_RS + 512)     // 99840

__device__ __align__(16) __nv_bfloat16 g_xcat[NTOT * KCAT];
__device__ __align__(16) __nv_bfloat16 g_dcat[NTOT * KCAT];
__device__ float g_xn2[NTOT];
__device__ float g_dn2[NTOT];

// --------------------------------------------------------------- PTX helpers
__device__ __forceinline__ uint32_t smem_u32(const void* p) {
    uint32_t a;
    asm("{ .reg .u64 t; cvta.to.shared.u64 t, %1; cvt.u32.u64 %0, t; }"
        : "=r"(a) : "l"(p));
    return a;
}

__device__ __forceinline__ void cp_async16(uint32_t sa, const void* ga) {
    asm volatile("cp.async.cg.shared.global [%0], [%1], 16;"
                 :: "r"(sa), "l"(ga) : "memory");
}
#define CP_COMMIT() asm volatile("cp.async.commit_group;" ::: "memory")

__device__ __forceinline__ float fast_ex2(float x) {
    float y;
    asm("ex2.approx.f32 %0, %1;" : "=f"(y) : "f"(x));
    return y;
}

#define LDMX4(r0, r1, r2, r3, adr)                                            \
    asm volatile("ldmatrix.sync.aligned.m8n8.x4.shared.b16 {%0,%1,%2,%3}, [%4];" \
                 : "=r"(r0), "=r"(r1), "=r"(r2), "=r"(r3) : "r"(adr))

#define MMA16816(cc, a0, a1, a2, a3, b0, b1)                                  \
    asm volatile("mma.sync.aligned.m16n8k16.row.col.f32.bf16.bf16.f32 "       \
                 "{%0,%1,%2,%3},{%4,%5,%6,%7},{%8,%9},{%0,%1,%2,%3};"         \
                 : "+f"((cc)[0]), "+f"((cc)[1]), "+f"((cc)[2]), "+f"((cc)[3]) \
                 : "r"(a0), "r"(a1), "r"(a2), "r"(a3), "r"(b0), "r"(b1))

#define LD_A(aa, adr) do {                                                    \
    LDMX4((aa)[0][0], (aa)[0][1], (aa)[0][2], (aa)[0][3], (adr));             \
    LDMX4((aa)[1][0], (aa)[1][1], (aa)[1][2], (aa)[1][3], (adr) + 2048);      \
    LDMX4((aa)[2][0], (aa)[2][1], (aa)[2][2], (aa)[2][3], (adr) + 4096);      \
    LDMX4((aa)[3][0], (aa)[3][1], (aa)[3][2], (aa)[3][3], (adr) + 6144);      \
} while (0)

#define LD_B(bb, adr) do {                                                    \
    uint32_t r0_, r1_, r2_, r3_;                                              \
    LDMX4(r0_, r1_, r2_, r3_, (adr));                                         \
    (bb)[0][0] = r0_; (bb)[0][1] = r2_; (bb)[1][0] = r1_; (bb)[1][1] = r3_;   \
    LDMX4(r0_, r1_, r2_, r3_, (adr) + 2048);                                  \
    (bb)[2][0] = r0_; (bb)[2][1] = r2_; (bb)[3][0] = r1_; (bb)[3][1] = r3_;   \
} while (0)

// -------------------------------------------------- convert + norms (warp/row)
__global__ void convert_kernel(const float* __restrict__ x,
                               const float* __restrict__ d) {
    const int gw   = (blockIdx.x * blockDim.x + threadIdx.x) >> 5;
    const int lane = threadIdx.x & 31;
    if (gw >= NTOT) return;

    {   // x row: [hi | hi | lo]
        float4 v = reinterpret_cast<const float4*>(x + (size_t)gw * DD)[lane];
        float nrm = v.x * v.x;
        nrm = fmaf(v.y, v.y, nrm);
        nrm = fmaf(v.z, v.z, nrm);
        nrm = fmaf(v.w, v.w, nrm);
        #pragma unroll
        for (int off = 16; off > 0; off >>= 1)
            nrm += __shfl_xor_sync(0xffffffffu, nrm, off);
        if (lane == 0) g_xn2[gw] = nrm;

        float f[4] = {v.x, v.y, v.z, v.w};
        unsigned short hb[4], lb[4];
        #pragma unroll
        for (int j = 0; j < 4; j++) {
            __nv_bfloat16 h = __float2bfloat16_rn(f[j]);
            __nv_bfloat16 l = __float2bfloat16_rn(f[j] - __bfloat162float(h));
            hb[j] = __bfloat16_as_ushort(h);
            lb[j] = __bfloat16_as_ushort(l);
        }
        uint2 hp = make_uint2((uint32_t)hb[0] | ((uint32_t)hb[1] << 16),
                              (uint32_t)hb[2] | ((uint32_t)hb[3] << 16));
        uint2 lp = make_uint2((uint32_t)lb[0] | ((uint32_t)lb[1] << 16),
                              (uint32_t)lb[2] | ((uint32_t)lb[3] << 16));
        char* base = reinterpret_cast<char*>(g_xcat) + (size_t)gw * 768 + lane * 8;
        *reinterpret_cast<uint2*>(base)       = hp;
        *reinterpret_cast<uint2*>(base + 256) = hp;
        *reinterpret_cast<uint2*>(base + 512) = lp;
    }
    {   // d row: [hi | lo | hi]
        float4 v = reinterpret_cast<const float4*>(d + (size_t)gw * DD)[lane];
        float nrm = v.x * v.x;
        nrm = fmaf(v.y, v.y, nrm);
        nrm = fmaf(v.z, v.z, nrm);
        nrm = fmaf(v.w, v.w, nrm);
        #pragma unroll
        for (int off = 16; off > 0; off >>= 1)
            nrm += __shfl_xor_sync(0xffffffffu, nrm, off);
        if (lane == 0) g_dn2[gw] = nrm;

        float f[4] = {v.x, v.y, v.z, v.w};
        unsigned short hb[4], lb[4];
        #pragma unroll
        for (int j = 0; j < 4; j++) {
            __nv_bfloat16 h = __float2bfloat16_rn(f[j]);
            __nv_bfloat16 l = __float2bfloat16_rn(f[j] - __bfloat162float(h));
            hb[j] = __bfloat16_as_ushort(h);
            lb[j] = __bfloat16_as_ushort(l);
        }
        uint2 hp = make_uint2((uint32_t)hb[0] | ((uint32_t)hb[1] << 16),
                              (uint32_t)hb[2] | ((uint32_t)hb[3] << 16));
        uint2 lp = make_uint2((uint32_t)lb[0] | ((uint32_t)lb[1] << 16),
                              (uint32_t)lb[2] | ((uint32_t)lb[3] << 16));
        char* base = reinterpret_cast<char*>(g_dcat) + (size_t)gw * 768 + lane * 8;
        *reinterpret_cast<uint2*>(base)       = hp;
        *reinterpret_cast<uint2*>(base + 256) = lp;
        *reinterpret_cast<uint2*>(base + 512) = hp;
    }
}

// ---------------------------------------------------------------- main kernel
__global__ void __launch_bounds__(256, 2)
kde_kernel(float* __restrict__ out) {
    extern __shared__ char smem[];
    const uint32_t sb = smem_u32(smem);
    const int tid  = threadIdx.x;
    const int lane = tid & 31;
    const int wid  = tid >> 5;
    const int wr   = wid & 1;      // n half (64 rows)
    const int wc   = wid >> 1;     // m quarter (32 cols)
    const int n0   = blockIdx.y * BN;
    const int m0   = blockIdx.x * BM;

    const float KEXP = -0.28777602743432504f;
    const float K2   =  0.57555205486865008f;

    float* cnS = reinterpret_cast<float*>(smem + SM_CN);
    float* cmS = reinterpret_cast<float*>(smem + SM_CM);
    float* rsS = reinterpret_cast<float*>(smem + SM_RS);

    if (tid < 128) {
        cnS[tid] = KEXP * g_xn2[n0 + tid];
        cmS[tid] = KEXP * g_dn2[m0 + tid];
        rsS[tid] = 0.f;
    }

    float c[4][4][4];
    #pragma unroll
    for (int rt = 0; rt < 4; rt++)
        #pragma unroll
        for (int ct = 0; ct < 4; ct++)
            #pragma unroll
            for (int q = 0; q < 4; q++)
                c[rt][ct][q] = 0.f;

    // ---- per-thread cp.async bases (all further addressing is immediate) ----
    const int row0 = tid >> 3;           // 0..31 (covers rows row0+32*i)
    const int w    = tid & 7;            // 16B segment within 128B k-chunk
    const char* gA0 = reinterpret_cast<const char*>(g_xcat) +
                      (size_t)(n0 + row0) * 768 + w * 16;
    const char* gB0 = reinterpret_cast<const char*>(g_dcat) +
                      (size_t)(m0 + row0) * 768 + w * 16;
    // swizzle term is i-invariant: (row0+32i)&7 == row0&7
    const uint32_t soff0 = row0 * 128 + ((w ^ (row0 & 7)) << 4);

    // ---- LDSM bases + precomputed swizzled k offsets ----
    const int h    = lane >> 4;
    const int rA   = wr * 64 + (lane & 15);
    const int rB   = wc * 32 + (lane & 15);
    const uint32_t sA0 = sb + rA * 128;          // + s*STG per stage
    const uint32_t sB0 = sb + ASZ + rB * 128;
    uint32_t kxA[4], kxB[4];
    #pragma unroll
    for (int k = 0; k < 4; k++) {
        kxA[k] = (uint32_t)(((2 * k + h) ^ (rA & 7)) << 4);
        kxB[k] = (uint32_t)(((2 * k + h) ^ (rB & 7)) << 4);
    }

    auto load_chunk = [&](int ch, int s) {
        const char* pa = gA0 + ch * 128;
        const char* pb = gB0 + ch * 128;
        const uint32_t da = sb + s * STG + soff0;
        const uint32_t db = da + ASZ;
        #pragma unroll
        for (int i = 0; i < 4; i++) {
            cp_async16(da + i * 4096, pa + (size_t)i * 24576);
            cp_async16(db + i * 4096, pb + (size_t)i * 24576);
        }
        CP_COMMIT();
    };

    auto compute_stage = [&](uint32_t sA, uint32_t sB) {
        uint32_t b[2][4][2];
        LD_B(b[0], sB + kxB[0]);
        #pragma unroll
        for (int k = 0; k < 4; k++) {
            uint32_t a[4][4];
            LD_A(a, sA + kxA[k]);
            if (k < 3) LD_B(b[(k + 1) & 1], sB + kxB[k + 1]);
            const int cur = k & 1;
            #pragma unroll
            for (int rt = 0; rt < 4; rt++)
                #pragma unroll
                for (int ct = 0; ct < 4; ct++)
                    MMA16816(c[rt][ct], a[rt][0], a[rt][1], a[rt][2], a[rt][3],
                             b[cur][ct][0], b[cur][ct][1]);
        }
    };

    // ---- 3-stage pipeline, fully unrolled, one __syncthreads per chunk ----
    load_chunk(0, 0);
    load_chunk(1, 1);

    #pragma unroll
    for (int ch = 0; ch < NCH; ch++) {
        if (ch < NCH - 1)
            asm volatile("cp.async.wait_group 1;" ::: "memory");
        else
            asm volatile("cp.async.wait_group 0;" ::: "memory");
        __syncthreads();
        const int s = ch % 3;
        compute_stage(sA0 + s * STG, sB0 + s * STG);
        if (ch + 2 < NCH) load_chunk(ch + 2, (ch + 2) % 3);
    }

    // --------- fused epilogue: exp2 + row reduce ---------
    const int rq = lane >> 2;
    const int cq = 2 * (lane & 3);
    #pragma unroll
    for (int rt = 0; rt < 4; rt++) {
        const int rbase = wr * 64 + rt * 16 + rq;
        const float cn0 = cnS[rbase];
        const float cn1 = cnS[rbase + 8];
        float s0 = 0.f, s1 = 0.f;
        #pragma unroll
        for (int ct = 0; ct < 4; ct++) {
            const int col = wc * 32 + ct * 8 + cq;
            const float cm0 = cmS[col], cm1 = cmS[col + 1];
            s0 += fast_ex2(fmaf(c[rt][ct][0], K2, cn0 + cm0));
            s0 += fast_ex2(fmaf(c[rt][ct][1], K2, cn0 + cm1));
            s1 += fast_ex2(fmaf(c[rt][ct][2], K2, cn1 + cm0));
            s1 += fast_ex2(fmaf(c[rt][ct][3], K2, cn1 + cm1));
        }
        s0 += __shfl_xor_sync(0xffffffffu, s0, 1);
        s0 += __shfl_xor_sync(0xffffffffu, s0, 2);
        s1 += __shfl_xor_sync(0xffffffffu, s1, 1);
        s1 += __shfl_xor_sync(0xffffffffu, s1, 2);
        if ((lane & 3) == 0) {
            atomicAdd(&rsS[rbase], s0);
            atomicAdd(&rsS[rbase + 8], s1);
        }
    }
    __syncthreads();
    if (tid < 128)
        atomicAdd(&out[n0 + tid], rsS[tid] * (1.0f / (float)NTOT));
}

extern "C" void kernel_launch(void* const* d_in, const int* in_sizes, int n_in,
                              void* d_out, int out_size) {
    const float* x    = (const float*)d_in[0];
    const float* data = (const float*)d_in[1];
    float* out = (float*)d_out;

    cudaFuncSetAttribute(kde_kernel,
                         cudaFuncAttributeMaxDynamicSharedMemorySize, SMEM_TOTAL);

    cudaMemsetAsync(d_out, 0, (size_t)out_size * sizeof(float));
    convert_kernel<<<NTOT * 32 / 256, 256>>>(x, data);

    dim3 grid(NTOT / BM, NTOT / BN);
    kde_kernel<<<grid, 256, SMEM_TOTAL>>>(out);
}